// round 13
// baseline (speedup 1.0000x reference)
#include <cuda_runtime.h>
#include <cuda_fp16.h>
#include <cstdint>
#include <cmath>

// ---------------------------------------------------------------------------
// Problem constants
// ---------------------------------------------------------------------------
#define Bb 4
#define Tt 4096
#define Dd 1024
#define Kk 64
#define Hh 4
#define KHh 16
#define Cc 64
#define MLPd 4096
#define Ntok (Bb * Tt)          // 16384 tokens

// ---------------------------------------------------------------------------
// Scratch (static __device__ arrays; no allocation anywhere)
// ---------------------------------------------------------------------------
__device__ __half g_xn  [(size_t)Ntok * Dd];
__device__ float  g_beta[(size_t)Ntok * 2 * Kk];
__device__ __half g_c   [(size_t)Ntok * 2 * Kk];
__device__ float  g_gate[(size_t)Ntok * Dd];
__device__ float  g_h   [(size_t)Ntok * Dd];
__device__ float  g_x1  [(size_t)Ntok * Dd];
__device__ __half g_x2  [(size_t)Ntok * Dd];
__device__ __half g_hid [(size_t)Ntok * MLPd];
// fp16 weights
__device__ __half g_win_h [2 * Kk * Dd];
__device__ __half g_wgt_h [Dd * Dd];
__device__ __half g_wout_h[Dd * 2 * Kk];
__device__ __half g_wm1_h [(size_t)MLPd * Dd];
__device__ __half g_wm2_h [(size_t)Dd * MLPd];

// ---------------------------------------------------------------------------
// Weight convert: fp32 -> fp16
// ---------------------------------------------------------------------------
__global__ void __launch_bounds__(256) wconv_kernel(
    const float* __restrict__ in, __half* __restrict__ out, int n4)
{
    int i = blockIdx.x * 256 + threadIdx.x;
    if (i >= n4) return;
    float4 v = ((const float4*)in)[i];
    size_t o = (size_t)i * 4;
    *(__half2*)&out[o]     = __floats2half2_rn(v.x, v.y);
    *(__half2*)&out[o + 2] = __floats2half2_rn(v.z, v.w);
}

// ---------------------------------------------------------------------------
// LayerNorm -> fp16 (one block per row of 1024)
// ---------------------------------------------------------------------------
__global__ void __launch_bounds__(256) ln_kernel(
    const float* __restrict__ x, const float* __restrict__ gg,
    const float* __restrict__ bb, __half* __restrict__ outh)
{
    int row = blockIdx.x;
    int tid = threadIdx.x;
    float4 v = ((const float4*)(x + (size_t)row * Dd))[tid];
    float s  = v.x + v.y + v.z + v.w;
    float ss = v.x*v.x + v.y*v.y + v.z*v.z + v.w*v.w;
    #pragma unroll
    for (int o = 16; o; o >>= 1) {
        s  += __shfl_down_sync(0xffffffffu, s,  o);
        ss += __shfl_down_sync(0xffffffffu, ss, o);
    }
    __shared__ float sh_s[8], sh_ss[8];
    __shared__ float sh_m, sh_r;
    int w = tid >> 5, lane = tid & 31;
    if (!lane) { sh_s[w] = s; sh_ss[w] = ss; }
    __syncthreads();
    if (tid == 0) {
        float S = 0.f, SS = 0.f;
        #pragma unroll
        for (int i = 0; i < 8; ++i) { S += sh_s[i]; SS += sh_ss[i]; }
        float m = S * (1.0f / Dd);
        sh_m = m;
        sh_r = rsqrtf(SS * (1.0f / Dd) - m * m + 1e-5f);
    }
    __syncthreads();
    float m = sh_m, r = sh_r;
    float4 g4 = ((const float4*)gg)[tid];
    float4 b4 = ((const float4*)bb)[tid];
    float ox = (v.x - m) * r * g4.x + b4.x;
    float oy = (v.y - m) * r * g4.y + b4.y;
    float oz = (v.z - m) * r * g4.z + b4.z;
    float ow = (v.w - m) * r * g4.w + b4.w;
    size_t o = (size_t)row * Dd + tid * 4;
    *(__half2*)&outh[o]     = __floats2half2_rn(ox, oy);
    *(__half2*)&outh[o + 2] = __floats2half2_rn(oz, ow);
}

// ---------------------------------------------------------------------------
// x1 = x + gate*h ; x2n = LN(x1) -> fp16.  One block per row.
// ---------------------------------------------------------------------------
__global__ void __launch_bounds__(256) combine_ln2_kernel(
    const float* __restrict__ x, const float* __restrict__ gate,
    const float* __restrict__ h, const float* __restrict__ g2,
    const float* __restrict__ b2, float* __restrict__ x1,
    __half* __restrict__ outh)
{
    int row = blockIdx.x;
    int tid = threadIdx.x;
    size_t off = (size_t)row * 256 + tid;
    float4 xv = ((const float4*)x)[off];
    float4 gv = ((const float4*)gate)[off];
    float4 hv = ((const float4*)h)[off];
    float4 v;
    v.x = xv.x + gv.x * hv.x;
    v.y = xv.y + gv.y * hv.y;
    v.z = xv.z + gv.z * hv.z;
    v.w = xv.w + gv.w * hv.w;
    ((float4*)x1)[off] = v;

    float s  = v.x + v.y + v.z + v.w;
    float ss = v.x*v.x + v.y*v.y + v.z*v.z + v.w*v.w;
    #pragma unroll
    for (int o = 16; o; o >>= 1) {
        s  += __shfl_down_sync(0xffffffffu, s,  o);
        ss += __shfl_down_sync(0xffffffffu, ss, o);
    }
    __shared__ float sh_s[8], sh_ss[8];
    __shared__ float sh_m, sh_r;
    int w = tid >> 5, lane = tid & 31;
    if (!lane) { sh_s[w] = s; sh_ss[w] = ss; }
    __syncthreads();
    if (tid == 0) {
        float S = 0.f, SS = 0.f;
        #pragma unroll
        for (int i = 0; i < 8; ++i) { S += sh_s[i]; SS += sh_ss[i]; }
        float m = S * (1.0f / Dd);
        sh_m = m;
        sh_r = rsqrtf(SS * (1.0f / Dd) - m * m + 1e-5f);
    }
    __syncthreads();
    float m = sh_m, r = sh_r;
    float4 g4 = ((const float4*)g2)[tid];
    float4 b4 = ((const float4*)b2)[tid];
    float ox = (v.x - m) * r * g4.x + b4.x;
    float oy = (v.y - m) * r * g4.y + b4.y;
    float oz = (v.z - m) * r * g4.z + b4.z;
    float ow = (v.w - m) * r * g4.w + b4.w;
    size_t o = off * 4;
    *(__half2*)&outh[o]     = __floats2half2_rn(ox, oy);
    *(__half2*)&outh[o + 2] = __floats2half2_rn(oz, ow);
}

// ---------------------------------------------------------------------------
// Phase A: intra-chunk BACKWARD complex scan, in place (fp32).
// ---------------------------------------------------------------------------
__global__ void __launch_bounds__(256) phaseA_kernel(
    float* __restrict__ beta, const float* __restrict__ ld,
    const float* __restrict__ fr)
{
    int tid = blockIdx.x * 256 + threadIdx.x;
    int k = tid & 63;
    int chunk = (tid >> 6) & 63;
    int b = tid >> 12;
    float mag = 1.0f / (1.0f + expf(-ld[k]));
    float f = fr[k];
    float lr = mag * cosf(f), li = mag * sinf(f);
    size_t base = ((size_t)(b * Tt + chunk * Cc)) * 128 + k;
    float cr = 0.f, ci = 0.f;
    for (int j = Cc - 1; j >= 0; --j) {
        size_t idx = base + (size_t)j * 128;
        float br = beta[idx];
        float bi = beta[idx + 64];
        float nr = br + lr * cr - li * ci;
        float ni = bi + lr * ci + li * cr;
        cr = nr; ci = ni;
        beta[idx]      = cr;
        beta[idx + 64] = ci;
    }
}

// ---------------------------------------------------------------------------
// Phase C: carry + 16x16 coupling -> fp16.  One block per token.
// ---------------------------------------------------------------------------
__global__ void __launch_bounds__(128) phaseC_kernel(
    const float* __restrict__ intra, const float* __restrict__ coup,
    __half* __restrict__ cout)
{
    int tg = blockIdx.x;
    int t = tg & (Tt - 1);
    int tid = threadIdx.x;

    __shared__ float cs[128];
    __shared__ float coups[Hh * KHh * KHh];
    #pragma unroll
    for (int i = tid; i < Hh * KHh * KHh; i += 128) coups[i] = coup[i];

    if (tid < 64) {
        int k = tid;
        size_t ib = (size_t)tg * 128 + k;
        float ir = intra[ib];
        float ii = intra[ib + 64];
        if (((t & (Cc - 1)) == 0) && (t > 0)) {
            size_t pb = (size_t)(tg - 1) * 128 + k;
            ir += intra[pb];
            ii += intra[pb + 64];
        }
        cs[k]      = ir;
        cs[64 + k] = ii;
    }
    __syncthreads();

    int m = tid;
    int part = m >> 6;
    int mm = m & 63;
    int hh = mm >> 4, j = mm & 15;
    const float* cp = &coups[(hh * KHh + j) * KHh];
    const float* cv = &cs[part * 64 + hh * KHh];
    float acc = 0.f;
    #pragma unroll
    for (int k = 0; k < KHh; ++k) acc += cp[k] * cv[k];
    cout[(size_t)tg * 128 + m] = __float2half_rn(acc);
}

// ---------------------------------------------------------------------------
// MMA helpers
// ---------------------------------------------------------------------------
__device__ __forceinline__ void ldsm_x4(uint32_t* r, uint32_t addr) {
    asm volatile("ldmatrix.sync.aligned.m8n8.x4.shared.b16 {%0,%1,%2,%3}, [%4];"
                 : "=r"(r[0]), "=r"(r[1]), "=r"(r[2]), "=r"(r[3]) : "r"(addr));
}
__device__ __forceinline__ void mma_f16(float* d, const uint32_t* a, const uint32_t* b) {
    asm volatile(
        "mma.sync.aligned.m16n8k16.row.col.f32.f16.f16.f32 "
        "{%0,%1,%2,%3}, {%4,%5,%6,%7}, {%8,%9}, {%0,%1,%2,%3};"
        : "+f"(d[0]), "+f"(d[1]), "+f"(d[2]), "+f"(d[3])
        : "r"(a[0]), "r"(a[1]), "r"(a[2]), "r"(a[3]), "r"(b[0]), "r"(b[1]));
}
__device__ __forceinline__ void cp16(uint32_t d, const void* s) {
    asm volatile("cp.async.cg.shared.global [%0], [%1], 16;" :: "r"(d), "l"(s));
}
__device__ __forceinline__ void cp_commit() {
    asm volatile("cp.async.commit_group;");
}
template <int Nn> __device__ __forceinline__ void cp_wait() {
    asm volatile("cp.async.wait_group %0;" :: "n"(Nn));
}

#define LDP 40                       // padded fp16 row stride

// ---------------------------------------------------------------------------
// Narrow GEMM (128x128 tile, warp 32x64) — used only for the small beta GEMM.
// ---------------------------------------------------------------------------
#define TSE (128 * LDP)
#define GEMM_SMEM_N (2 * 2 * TSE * 2)   // 40960 B

__global__ void __launch_bounds__(256) mma_gemm_narrow(
    const __half* __restrict__ A, const __half* __restrict__ Wh,
    float* __restrict__ Cout, int M, int N, int Kd)
{
    extern __shared__ __half sm[];

    int t = threadIdx.x;
    int lane = t & 31, w = t >> 5;
    int wm = (w & 3) * 32;
    int wn = (w >> 2) * 64;
    int m0 = blockIdx.y * 128;
    int n0 = blockIdx.x * 128;

    int a_row = wm + (lane & 15);
    int a_coladd = (lane >> 4) << 3;
    int b_row = wn + (lane & 7) + ((lane >> 4) << 3);
    int b_coladd = ((lane >> 3) & 1) << 3;

    uint32_t sbase = (uint32_t)__cvta_generic_to_shared(sm);

    float acc[2][8][4];
    #pragma unroll
    for (int i = 0; i < 2; ++i)
        #pragma unroll
        for (int j = 0; j < 8; ++j)
            #pragma unroll
            for (int e = 0; e < 4; ++e) acc[i][j][e] = 0.f;

    int nk = Kd >> 5;

    auto issue_stage = [&](int s, int kt) {
        uint32_t stb = sbase + (uint32_t)s * (2u * TSE * 2u);
        int k0 = kt * 32;
        #pragma unroll
        for (int it = 0; it < 2; ++it) {
            int c = t + it * 256;
            int row = c >> 2;
            int off8 = (c & 3) * 8;
            uint32_t dsto = (uint32_t)(row * LDP + off8) * 2u;
            cp16(stb + dsto,                       A  + (size_t)(m0 + row) * Kd + k0 + off8);
            cp16(stb + (uint32_t)(TSE * 2) + dsto, Wh + (size_t)(n0 + row) * Kd + k0 + off8);
        }
        cp_commit();
    };

    issue_stage(0, 0);

    for (int kt = 0; kt < nk; ++kt) {
        int s = kt & 1;
        if (kt + 1 < nk) { issue_stage(1 - s, kt + 1); cp_wait<1>(); }
        else             { cp_wait<0>(); }
        __syncthreads();

        uint32_t stb = sbase + (uint32_t)s * (2u * TSE * 2u);
        #pragma unroll
        for (int kk = 0; kk < 32; kk += 16) {
            uint32_t Af[2][4], Bf[4][4];
            #pragma unroll
            for (int im = 0; im < 2; ++im) {
                uint32_t off = (uint32_t)((a_row + im * 16) * LDP + kk + a_coladd) * 2;
                ldsm_x4(Af[im], stb + off);
            }
            #pragma unroll
            for (int q = 0; q < 4; ++q) {
                uint32_t off = (uint32_t)((b_row + q * 16) * LDP + kk + b_coladd) * 2;
                ldsm_x4(Bf[q], stb + (uint32_t)(TSE * 2) + off);
            }
            #pragma unroll
            for (int im = 0; im < 2; ++im)
                #pragma unroll
                for (int q = 0; q < 4; ++q)
                    #pragma unroll
                    for (int hf = 0; hf < 2; ++hf)
                        mma_f16(acc[im][q * 2 + hf], Af[im], &Bf[q][hf * 2]);
        }
        __syncthreads();
    }

    #pragma unroll
    for (int im = 0; im < 2; ++im) {
        int r0 = m0 + wm + im * 16 + (lane >> 2);
        #pragma unroll
        for (int jn = 0; jn < 8; ++jn) {
            int c0 = n0 + wn + jn * 8 + (lane & 3) * 2;
            size_t o0 = (size_t)r0 * N + c0;
            size_t o1 = (size_t)(r0 + 8) * N + c0;
            *(float2*)&Cout[o0] = make_float2(acc[im][jn][0], acc[im][jn][1]);
            *(float2*)&Cout[o1] = make_float2(acc[im][jn][2], acc[im][jn][3]);
        }
    }
}

// ---------------------------------------------------------------------------
// Wide GEMM: 128x256 CTA tile, 8 warps 2(m)x4(n), warp tile 64x64.
//   Per kk=16: 8 LDSM feed 32 HMMA (4 MMA/LDSM vs 2.67 narrow).
// Dynamic smem: 2 stages x (128+256)x40 fp16 = 60 KB.
// EPI: 0 fp32; 1 sigmoid(z+b); 2 silu(z+b)->fp16; 3 z+b+res
// ---------------------------------------------------------------------------
#define ASE (128 * LDP)
#define BSE (256 * LDP)
#define STGW ((ASE + BSE) * 2)          // 30720 B per stage
#define GEMM_SMEM_W (2 * STGW)          // 61440 B

template <int EPI>
__global__ void __launch_bounds__(256) mma_gemm_wide(
    const __half* __restrict__ A, const __half* __restrict__ Wh,
    const float* __restrict__ bias, const float* __restrict__ res,
    float* __restrict__ Cout, __half* __restrict__ Ch,
    int M, int N, int Kd)
{
    extern __shared__ __half sm[];

    int t = threadIdx.x;
    int lane = t & 31, w = t >> 5;
    int wm = (w & 1) * 64;
    int wn = (w >> 1) * 64;
    int m0 = blockIdx.y * 128;
    int n0 = blockIdx.x * 256;

    int a_row = wm + (lane & 15);
    int a_coladd = (lane >> 4) << 3;
    int b_row = wn + (lane & 7) + ((lane >> 4) << 3);
    int b_coladd = ((lane >> 3) & 1) << 3;

    uint32_t sbase = (uint32_t)__cvta_generic_to_shared(sm);

    float acc[4][8][4];
    #pragma unroll
    for (int i = 0; i < 4; ++i)
        #pragma unroll
        for (int j = 0; j < 8; ++j)
            #pragma unroll
            for (int e = 0; e < 4; ++e) acc[i][j][e] = 0.f;

    int nk = Kd >> 5;

    auto issue_stage = [&](int s, int kt) {
        uint32_t stb = sbase + (uint32_t)s * STGW;
        int k0 = kt * 32;
        // A: 128 rows x 4 chunks = 512
        #pragma unroll
        for (int it = 0; it < 2; ++it) {
            int c = t + it * 256;
            int row = c >> 2;
            int off8 = (c & 3) * 8;
            uint32_t dsto = (uint32_t)(row * LDP + off8) * 2u;
            cp16(stb + dsto, A + (size_t)(m0 + row) * Kd + k0 + off8);
        }
        // B: 256 rows x 4 chunks = 1024
        #pragma unroll
        for (int it = 0; it < 4; ++it) {
            int c = t + it * 256;
            int row = c >> 2;
            int off8 = (c & 3) * 8;
            uint32_t dsto = (uint32_t)(ASE * 2) + (uint32_t)(row * LDP + off8) * 2u;
            cp16(stb + dsto, Wh + (size_t)(n0 + row) * Kd + k0 + off8);
        }
        cp_commit();
    };

    issue_stage(0, 0);

    for (int kt = 0; kt < nk; ++kt) {
        int s = kt & 1;
        if (kt + 1 < nk) { issue_stage(1 - s, kt + 1); cp_wait<1>(); }
        else             { cp_wait<0>(); }
        __syncthreads();

        uint32_t stb = sbase + (uint32_t)s * STGW;
        #pragma unroll
        for (int kk = 0; kk < 32; kk += 16) {
            uint32_t Af[4][4], Bf[4][4];
            #pragma unroll
            for (int im = 0; im < 4; ++im) {
                uint32_t off = (uint32_t)((a_row + im * 16) * LDP + kk + a_coladd) * 2;
                ldsm_x4(Af[im], stb + off);
            }
            #pragma unroll
            for (int q = 0; q < 4; ++q) {
                uint32_t off = (uint32_t)(ASE * 2)
                             + (uint32_t)((b_row + q * 16) * LDP + kk + b_coladd) * 2;
                ldsm_x4(Bf[q], stb + off);
            }
            #pragma unroll
            for (int im = 0; im < 4; ++im)
                #pragma unroll
                for (int q = 0; q < 4; ++q)
                    #pragma unroll
                    for (int hf = 0; hf < 2; ++hf)
                        mma_f16(acc[im][q * 2 + hf], Af[im], &Bf[q][hf * 2]);
        }
        __syncthreads();
    }

    // epilogue
    #pragma unroll
    for (int im = 0; im < 4; ++im) {
        int r0 = m0 + wm + im * 16 + (lane >> 2);
        #pragma unroll
        for (int jn = 0; jn < 8; ++jn) {
            int c0 = n0 + wn + jn * 8 + (lane & 3) * 2;
            float b0 = 0.f, b1 = 0.f;
            if (EPI != 0) { b0 = bias[c0]; b1 = bias[c0 + 1]; }
            float z[4] = {acc[im][jn][0], acc[im][jn][1],
                          acc[im][jn][2], acc[im][jn][3]};
            #pragma unroll
            for (int e = 0; e < 4; ++e) {
                float bb = (e & 1) ? b1 : b0;
                float v = z[e];
                if (EPI == 1) { v += bb; v = 1.0f / (1.0f + expf(-v)); }
                else if (EPI == 2) { v += bb; v = v / (1.0f + expf(-v)); }
                z[e] = v;
            }
            size_t o0 = (size_t)r0 * N + c0;
            size_t o1 = (size_t)(r0 + 8) * N + c0;
            if (EPI == 2) {
                *(__half2*)&Ch[o0] = __floats2half2_rn(z[0], z[1]);
                *(__half2*)&Ch[o1] = __floats2half2_rn(z[2], z[3]);
            } else {
                if (EPI == 3) {
                    z[0] += b0 + res[o0]; z[1] += b1 + res[o0 + 1];
                    z[2] += b0 + res[o1]; z[3] += b1 + res[o1 + 1];
                }
                *(float2*)&Cout[o0] = make_float2(z[0], z[1]);
                *(float2*)&Cout[o1] = make_float2(z[2], z[3]);
            }
        }
    }
}

// ---------------------------------------------------------------------------
// Launch
// ---------------------------------------------------------------------------
extern "C" void kernel_launch(void* const* d_in, const int* in_sizes, int n_in,
                              void* d_out, int out_size)
{
    const float* x         = (const float*)d_in[0];
    const float* w_in      = (const float*)d_in[1];
    const float* w_out     = (const float*)d_in[2];
    const float* w_gate    = (const float*)d_in[3];
    const float* b_gate    = (const float*)d_in[4];
    const float* log_decay = (const float*)d_in[5];
    const float* frequency = (const float*)d_in[6];
    const float* coupling  = (const float*)d_in[7];
    const float* w_mlp1    = (const float*)d_in[8];
    const float* b_mlp1    = (const float*)d_in[9];
    const float* w_mlp2    = (const float*)d_in[10];
    const float* b_mlp2    = (const float*)d_in[11];
    const float* ln1_g     = (const float*)d_in[12];
    const float* ln1_b     = (const float*)d_in[13];
    const float* ln2_g     = (const float*)d_in[14];
    const float* ln2_b     = (const float*)d_in[15];
    float* out = (float*)d_out;

    __half *xn, *cb, *x2, *hid;
    __half *winh, *wgth, *wouth, *wm1h, *wm2h;
    float *beta, *gate, *hbuf, *x1;
    cudaGetSymbolAddress((void**)&xn,   g_xn);
    cudaGetSymbolAddress((void**)&beta, g_beta);
    cudaGetSymbolAddress((void**)&cb,   g_c);
    cudaGetSymbolAddress((void**)&gate, g_gate);
    cudaGetSymbolAddress((void**)&hbuf, g_h);
    cudaGetSymbolAddress((void**)&x1,   g_x1);
    cudaGetSymbolAddress((void**)&x2,   g_x2);
    cudaGetSymbolAddress((void**)&hid,  g_hid);
    cudaGetSymbolAddress((void**)&winh,  g_win_h);
    cudaGetSymbolAddress((void**)&wgth,  g_wgt_h);
    cudaGetSymbolAddress((void**)&wouth, g_wout_h);
    cudaGetSymbolAddress((void**)&wm1h,  g_wm1_h);
    cudaGetSymbolAddress((void**)&wm2h,  g_wm2_h);

    cudaFuncSetAttribute(mma_gemm_narrow,  cudaFuncAttributeMaxDynamicSharedMemorySize, GEMM_SMEM_N);
    cudaFuncSetAttribute(mma_gemm_wide<0>, cudaFuncAttributeMaxDynamicSharedMemorySize, GEMM_SMEM_W);
    cudaFuncSetAttribute(mma_gemm_wide<1>, cudaFuncAttributeMaxDynamicSharedMemorySize, GEMM_SMEM_W);
    cudaFuncSetAttribute(mma_gemm_wide<2>, cudaFuncAttributeMaxDynamicSharedMemorySize, GEMM_SMEM_W);
    cudaFuncSetAttribute(mma_gemm_wide<3>, cudaFuncAttributeMaxDynamicSharedMemorySize, GEMM_SMEM_W);

    // 0. weights -> fp16
    wconv_kernel<<<(2*Kk*Dd/4 + 255)/256, 256>>>(w_in,   winh,  2*Kk*Dd/4);
    wconv_kernel<<<(Dd*Dd/4 + 255)/256, 256>>>(w_gate,  wgth,  Dd*Dd/4);
    wconv_kernel<<<(Dd*2*Kk/4 + 255)/256, 256>>>(w_out, wouth, Dd*2*Kk/4);
    wconv_kernel<<<(MLPd*Dd/4 + 255)/256, 256>>>(w_mlp1, wm1h, MLPd*Dd/4);
    wconv_kernel<<<(Dd*MLPd/4 + 255)/256, 256>>>(w_mlp2, wm2h, Dd*MLPd/4);

    // 1. LN1 -> xnorm fp16
    ln_kernel<<<Ntok, 256>>>(x, ln1_g, ln1_b, xn);
    // 2. beta = xnorm @ w_in^T   (16384 x 128 x 1024), narrow kernel
    mma_gemm_narrow<<<dim3(1, Ntok/128), 256, GEMM_SMEM_N>>>(
        xn, winh, beta, Ntok, 128, Dd);
    // 3. intra-chunk backward scan (in place, fp32)
    phaseA_kernel<<<64, 256>>>(beta, log_decay, frequency);
    // 4. carry + coupling -> c fp16
    phaseC_kernel<<<Ntok, 128>>>(beta, coupling, cb);
    // 5. gate = sigmoid(xnorm @ w_gate^T + b_gate)
    mma_gemm_wide<1><<<dim3(Dd/256, Ntok/128), 256, GEMM_SMEM_W>>>(
        xn, wgth, b_gate, nullptr, gate, nullptr, Ntok, Dd, Dd);
    // 6. h = c @ w_out^T   (K = 128)
    mma_gemm_wide<0><<<dim3(Dd/256, Ntok/128), 256, GEMM_SMEM_W>>>(
        cb, wouth, nullptr, nullptr, hbuf, nullptr, Ntok, Dd, 2*Kk);
    // 7. x1 = x + gate*h ; x2n = LN2(x1) -> fp16
    combine_ln2_kernel<<<Ntok, 256>>>(x, gate, hbuf, ln2_g, ln2_b, x1, x2);
    // 8. hid = silu(x2n @ w_mlp1^T + b1) -> fp16
    mma_gemm_wide<2><<<dim3(MLPd/256, Ntok/128), 256, GEMM_SMEM_W>>>(
        x2, wm1h, b_mlp1, nullptr, nullptr, hid, Ntok, MLPd, Dd);
    // 9. out = hid @ w_mlp2^T + b2 + x1
    mma_gemm_wide<3><<<dim3(Dd/256, Ntok/128), 256, GEMM_SMEM_W>>>(
        hid, wm2h, b_mlp2, x1, out, nullptr, Ntok, Dd, MLPd);
    (void)in_sizes; (void)n_in; (void)out_size;
}

// round 14
// speedup vs baseline: 1.0473x; 1.0473x over previous
#include <cuda_runtime.h>
#include <cuda_fp16.h>
#include <cstdint>
#include <cmath>

// ---------------------------------------------------------------------------
// Problem constants
// ---------------------------------------------------------------------------
#define Bb 4
#define Tt 4096
#define Dd 1024
#define Kk 64
#define Hh 4
#define KHh 16
#define Cc 64
#define MLPd 4096
#define Ntok (Bb * Tt)          // 16384 tokens

// ---------------------------------------------------------------------------
// Scratch (static __device__ arrays; no allocation anywhere)
// ---------------------------------------------------------------------------
__device__ __half g_xn  [(size_t)Ntok * Dd];
__device__ float  g_beta[(size_t)Ntok * 2 * Kk];
__device__ __half g_c   [(size_t)Ntok * 2 * Kk];
__device__ float  g_gate[(size_t)Ntok * Dd];
__device__ float  g_h   [(size_t)Ntok * Dd];
__device__ float  g_x1  [(size_t)Ntok * Dd];
__device__ __half g_x2  [(size_t)Ntok * Dd];
__device__ __half g_hid [(size_t)Ntok * MLPd];
// fp16 weights
__device__ __half g_win_h [2 * Kk * Dd];
__device__ __half g_wgt_h [Dd * Dd];
__device__ __half g_wout_h[Dd * 2 * Kk];
__device__ __half g_wm1_h [(size_t)MLPd * Dd];
__device__ __half g_wm2_h [(size_t)Dd * MLPd];

// ---------------------------------------------------------------------------
// Weight convert: fp32 -> fp16
// ---------------------------------------------------------------------------
__global__ void __launch_bounds__(256) wconv_kernel(
    const float* __restrict__ in, __half* __restrict__ out, int n4)
{
    int i = blockIdx.x * 256 + threadIdx.x;
    if (i >= n4) return;
    float4 v = ((const float4*)in)[i];
    size_t o = (size_t)i * 4;
    *(__half2*)&out[o]     = __floats2half2_rn(v.x, v.y);
    *(__half2*)&out[o + 2] = __floats2half2_rn(v.z, v.w);
}

// ---------------------------------------------------------------------------
// LayerNorm -> fp16 (one block per row of 1024)
// ---------------------------------------------------------------------------
__global__ void __launch_bounds__(256) ln_kernel(
    const float* __restrict__ x, const float* __restrict__ gg,
    const float* __restrict__ bb, __half* __restrict__ outh)
{
    int row = blockIdx.x;
    int tid = threadIdx.x;
    float4 v = ((const float4*)(x + (size_t)row * Dd))[tid];
    float s  = v.x + v.y + v.z + v.w;
    float ss = v.x*v.x + v.y*v.y + v.z*v.z + v.w*v.w;
    #pragma unroll
    for (int o = 16; o; o >>= 1) {
        s  += __shfl_down_sync(0xffffffffu, s,  o);
        ss += __shfl_down_sync(0xffffffffu, ss, o);
    }
    __shared__ float sh_s[8], sh_ss[8];
    __shared__ float sh_m, sh_r;
    int w = tid >> 5, lane = tid & 31;
    if (!lane) { sh_s[w] = s; sh_ss[w] = ss; }
    __syncthreads();
    if (tid == 0) {
        float S = 0.f, SS = 0.f;
        #pragma unroll
        for (int i = 0; i < 8; ++i) { S += sh_s[i]; SS += sh_ss[i]; }
        float m = S * (1.0f / Dd);
        sh_m = m;
        sh_r = rsqrtf(SS * (1.0f / Dd) - m * m + 1e-5f);
    }
    __syncthreads();
    float m = sh_m, r = sh_r;
    float4 g4 = ((const float4*)gg)[tid];
    float4 b4 = ((const float4*)bb)[tid];
    float ox = (v.x - m) * r * g4.x + b4.x;
    float oy = (v.y - m) * r * g4.y + b4.y;
    float oz = (v.z - m) * r * g4.z + b4.z;
    float ow = (v.w - m) * r * g4.w + b4.w;
    size_t o = (size_t)row * Dd + tid * 4;
    *(__half2*)&outh[o]     = __floats2half2_rn(ox, oy);
    *(__half2*)&outh[o + 2] = __floats2half2_rn(oz, ow);
}

// ---------------------------------------------------------------------------
// x1 = x + gate*h ; x2n = LN(x1) -> fp16.  One block per row.
// ---------------------------------------------------------------------------
__global__ void __launch_bounds__(256) combine_ln2_kernel(
    const float* __restrict__ x, const float* __restrict__ gate,
    const float* __restrict__ h, const float* __restrict__ g2,
    const float* __restrict__ b2, float* __restrict__ x1,
    __half* __restrict__ outh)
{
    int row = blockIdx.x;
    int tid = threadIdx.x;
    size_t off = (size_t)row * 256 + tid;
    float4 xv = ((const float4*)x)[off];
    float4 gv = ((const float4*)gate)[off];
    float4 hv = ((const float4*)h)[off];
    float4 v;
    v.x = xv.x + gv.x * hv.x;
    v.y = xv.y + gv.y * hv.y;
    v.z = xv.z + gv.z * hv.z;
    v.w = xv.w + gv.w * hv.w;
    ((float4*)x1)[off] = v;

    float s  = v.x + v.y + v.z + v.w;
    float ss = v.x*v.x + v.y*v.y + v.z*v.z + v.w*v.w;
    #pragma unroll
    for (int o = 16; o; o >>= 1) {
        s  += __shfl_down_sync(0xffffffffu, s,  o);
        ss += __shfl_down_sync(0xffffffffu, ss, o);
    }
    __shared__ float sh_s[8], sh_ss[8];
    __shared__ float sh_m, sh_r;
    int w = tid >> 5, lane = tid & 31;
    if (!lane) { sh_s[w] = s; sh_ss[w] = ss; }
    __syncthreads();
    if (tid == 0) {
        float S = 0.f, SS = 0.f;
        #pragma unroll
        for (int i = 0; i < 8; ++i) { S += sh_s[i]; SS += sh_ss[i]; }
        float m = S * (1.0f / Dd);
        sh_m = m;
        sh_r = rsqrtf(SS * (1.0f / Dd) - m * m + 1e-5f);
    }
    __syncthreads();
    float m = sh_m, r = sh_r;
    float4 g4 = ((const float4*)g2)[tid];
    float4 b4 = ((const float4*)b2)[tid];
    float ox = (v.x - m) * r * g4.x + b4.x;
    float oy = (v.y - m) * r * g4.y + b4.y;
    float oz = (v.z - m) * r * g4.z + b4.z;
    float ow = (v.w - m) * r * g4.w + b4.w;
    size_t o = off * 4;
    *(__half2*)&outh[o]     = __floats2half2_rn(ox, oy);
    *(__half2*)&outh[o + 2] = __floats2half2_rn(oz, ow);
}

// ---------------------------------------------------------------------------
// Phase A: intra-chunk BACKWARD complex scan, in place (fp32).
// ---------------------------------------------------------------------------
__global__ void __launch_bounds__(256) phaseA_kernel(
    float* __restrict__ beta, const float* __restrict__ ld,
    const float* __restrict__ fr)
{
    int tid = blockIdx.x * 256 + threadIdx.x;
    int k = tid & 63;
    int chunk = (tid >> 6) & 63;
    int b = tid >> 12;
    float mag = 1.0f / (1.0f + expf(-ld[k]));
    float f = fr[k];
    float lr = mag * cosf(f), li = mag * sinf(f);
    size_t base = ((size_t)(b * Tt + chunk * Cc)) * 128 + k;
    float cr = 0.f, ci = 0.f;
    for (int j = Cc - 1; j >= 0; --j) {
        size_t idx = base + (size_t)j * 128;
        float br = beta[idx];
        float bi = beta[idx + 64];
        float nr = br + lr * cr - li * ci;
        float ni = bi + lr * ci + li * cr;
        cr = nr; ci = ni;
        beta[idx]      = cr;
        beta[idx + 64] = ci;
    }
}

// ---------------------------------------------------------------------------
// Phase C: carry + 16x16 coupling -> fp16.  One block per token.
// ---------------------------------------------------------------------------
__global__ void __launch_bounds__(128) phaseC_kernel(
    const float* __restrict__ intra, const float* __restrict__ coup,
    __half* __restrict__ cout)
{
    int tg = blockIdx.x;
    int t = tg & (Tt - 1);
    int tid = threadIdx.x;

    __shared__ float cs[128];
    __shared__ float coups[Hh * KHh * KHh];
    #pragma unroll
    for (int i = tid; i < Hh * KHh * KHh; i += 128) coups[i] = coup[i];

    if (tid < 64) {
        int k = tid;
        size_t ib = (size_t)tg * 128 + k;
        float ir = intra[ib];
        float ii = intra[ib + 64];
        if (((t & (Cc - 1)) == 0) && (t > 0)) {
            size_t pb = (size_t)(tg - 1) * 128 + k;
            ir += intra[pb];
            ii += intra[pb + 64];
        }
        cs[k]      = ir;
        cs[64 + k] = ii;
    }
    __syncthreads();

    int m = tid;
    int part = m >> 6;
    int mm = m & 63;
    int hh = mm >> 4, j = mm & 15;
    const float* cp = &coups[(hh * KHh + j) * KHh];
    const float* cv = &cs[part * 64 + hh * KHh];
    float acc = 0.f;
    #pragma unroll
    for (int k = 0; k < KHh; ++k) acc += cp[k] * cv[k];
    cout[(size_t)tg * 128 + m] = __float2half_rn(acc);
}

// ---------------------------------------------------------------------------
// MMA helpers
// ---------------------------------------------------------------------------
__device__ __forceinline__ void ldsm_x4(uint32_t* r, uint32_t addr) {
    asm volatile("ldmatrix.sync.aligned.m8n8.x4.shared.b16 {%0,%1,%2,%3}, [%4];"
                 : "=r"(r[0]), "=r"(r[1]), "=r"(r[2]), "=r"(r[3]) : "r"(addr));
}
__device__ __forceinline__ void mma_f16(float* d, const uint32_t* a, const uint32_t* b) {
    asm volatile(
        "mma.sync.aligned.m16n8k16.row.col.f32.f16.f16.f32 "
        "{%0,%1,%2,%3}, {%4,%5,%6,%7}, {%8,%9}, {%0,%1,%2,%3};"
        : "+f"(d[0]), "+f"(d[1]), "+f"(d[2]), "+f"(d[3])
        : "r"(a[0]), "r"(a[1]), "r"(a[2]), "r"(a[3]), "r"(b[0]), "r"(b[1]));
}
__device__ __forceinline__ void cp16(uint32_t d, const void* s) {
    asm volatile("cp.async.cg.shared.global [%0], [%1], 16;" :: "r"(d), "l"(s));
}
__device__ __forceinline__ void cp_commit() {
    asm volatile("cp.async.commit_group;");
}
template <int Nn> __device__ __forceinline__ void cp_wait() {
    asm volatile("cp.async.wait_group %0;" :: "n"(Nn));
}

#define LDP 40                       // padded fp16 row stride

// ---------------------------------------------------------------------------
// Narrow GEMM (128x128 tile, 256 thr, warp 32x64) — only for the beta GEMM.
// ---------------------------------------------------------------------------
#define TSE (128 * LDP)
#define GEMM_SMEM_N (2 * 2 * TSE * 2)   // 40960 B

__global__ void __launch_bounds__(256) mma_gemm_narrow(
    const __half* __restrict__ A, const __half* __restrict__ Wh,
    float* __restrict__ Cout, int M, int N, int Kd)
{
    extern __shared__ __half sm[];

    int t = threadIdx.x;
    int lane = t & 31, w = t >> 5;
    int wm = (w & 3) * 32;
    int wn = (w >> 2) * 64;
    int m0 = blockIdx.y * 128;
    int n0 = blockIdx.x * 128;

    int a_row = wm + (lane & 15);
    int a_coladd = (lane >> 4) << 3;
    int b_row = wn + (lane & 7) + ((lane >> 4) << 3);
    int b_coladd = ((lane >> 3) & 1) << 3;

    uint32_t sbase = (uint32_t)__cvta_generic_to_shared(sm);

    float acc[2][8][4];
    #pragma unroll
    for (int i = 0; i < 2; ++i)
        #pragma unroll
        for (int j = 0; j < 8; ++j)
            #pragma unroll
            for (int e = 0; e < 4; ++e) acc[i][j][e] = 0.f;

    int nk = Kd >> 5;

    auto issue_stage = [&](int s, int kt) {
        uint32_t stb = sbase + (uint32_t)s * (2u * TSE * 2u);
        int k0 = kt * 32;
        #pragma unroll
        for (int it = 0; it < 2; ++it) {
            int c = t + it * 256;
            int row = c >> 2;
            int off8 = (c & 3) * 8;
            uint32_t dsto = (uint32_t)(row * LDP + off8) * 2u;
            cp16(stb + dsto,                       A  + (size_t)(m0 + row) * Kd + k0 + off8);
            cp16(stb + (uint32_t)(TSE * 2) + dsto, Wh + (size_t)(n0 + row) * Kd + k0 + off8);
        }
        cp_commit();
    };

    issue_stage(0, 0);

    for (int kt = 0; kt < nk; ++kt) {
        int s = kt & 1;
        if (kt + 1 < nk) { issue_stage(1 - s, kt + 1); cp_wait<1>(); }
        else             { cp_wait<0>(); }
        __syncthreads();

        uint32_t stb = sbase + (uint32_t)s * (2u * TSE * 2u);
        #pragma unroll
        for (int kk = 0; kk < 32; kk += 16) {
            uint32_t Af[2][4], Bf[4][4];
            #pragma unroll
            for (int im = 0; im < 2; ++im) {
                uint32_t off = (uint32_t)((a_row + im * 16) * LDP + kk + a_coladd) * 2;
                ldsm_x4(Af[im], stb + off);
            }
            #pragma unroll
            for (int q = 0; q < 4; ++q) {
                uint32_t off = (uint32_t)((b_row + q * 16) * LDP + kk + b_coladd) * 2;
                ldsm_x4(Bf[q], stb + (uint32_t)(TSE * 2) + off);
            }
            #pragma unroll
            for (int im = 0; im < 2; ++im)
                #pragma unroll
                for (int q = 0; q < 4; ++q)
                    #pragma unroll
                    for (int hf = 0; hf < 2; ++hf)
                        mma_f16(acc[im][q * 2 + hf], Af[im], &Bf[q][hf * 2]);
        }
        __syncthreads();
    }

    #pragma unroll
    for (int im = 0; im < 2; ++im) {
        int r0 = m0 + wm + im * 16 + (lane >> 2);
        #pragma unroll
        for (int jn = 0; jn < 8; ++jn) {
            int c0 = n0 + wn + jn * 8 + (lane & 3) * 2;
            size_t o0 = (size_t)r0 * N + c0;
            size_t o1 = (size_t)(r0 + 8) * N + c0;
            *(float2*)&Cout[o0] = make_float2(acc[im][jn][0], acc[im][jn][1]);
            *(float2*)&Cout[o1] = make_float2(acc[im][jn][2], acc[im][jn][3]);
        }
    }
}

// ---------------------------------------------------------------------------
// Big-M GEMM: 256(M)x128(N) CTA tile, 512 threads, 16 warps (8m x 2n),
// warp tile 32x64 (same 64 acc/thread as the validated Round-12 kernel).
// Halves B-operand L2 reloads; 3-stage cp.async pipeline covers the single-
// CTA-per-SM sync gaps.  Smem: 3 stages x (256+128)x40 fp16 = 90 KB.
// EPI: 0 fp32; 1 sigmoid(z+b); 2 silu(z+b)->fp16; 3 z+b+res
// ---------------------------------------------------------------------------
#define ASE2 (256 * LDP)
#define BSE2 (128 * LDP)
#define STG2 ((ASE2 + BSE2) * 2)        // 30720 B per stage
#define GEMM_SMEM_B (3 * STG2)          // 92160 B

template <int EPI>
__global__ void __launch_bounds__(512) mma_gemm_bigm(
    const __half* __restrict__ A, const __half* __restrict__ Wh,
    const float* __restrict__ bias, const float* __restrict__ res,
    float* __restrict__ Cout, __half* __restrict__ Ch,
    int M, int N, int Kd)
{
    extern __shared__ __half sm[];

    int t = threadIdx.x;
    int lane = t & 31, w = t >> 5;          // 16 warps
    int wm = (w & 7) * 32;                  // 8 in m
    int wn = (w >> 3) * 64;                 // 2 in n
    int m0 = blockIdx.y * 256;
    int n0 = blockIdx.x * 128;

    int a_row = wm + (lane & 15);
    int a_coladd = (lane >> 4) << 3;
    int b_row = wn + (lane & 7) + ((lane >> 4) << 3);
    int b_coladd = ((lane >> 3) & 1) << 3;

    uint32_t sbase = (uint32_t)__cvta_generic_to_shared(sm);

    float acc[2][8][4];
    #pragma unroll
    for (int i = 0; i < 2; ++i)
        #pragma unroll
        for (int j = 0; j < 8; ++j)
            #pragma unroll
            for (int e = 0; e < 4; ++e) acc[i][j][e] = 0.f;

    int nk = Kd >> 5;

    auto issue_stage = [&](int s, int kt) {
        uint32_t stb = sbase + (uint32_t)s * STG2;
        int k0 = kt * 32;
        // A: 256 rows x 4 chunks = 1024
        #pragma unroll
        for (int it = 0; it < 2; ++it) {
            int c = t + it * 512;
            int row = c >> 2;
            int off8 = (c & 3) * 8;
            uint32_t dsto = (uint32_t)(row * LDP + off8) * 2u;
            cp16(stb + dsto, A + (size_t)(m0 + row) * Kd + k0 + off8);
        }
        // B: 128 rows x 4 chunks = 512
        {
            int c = t;
            int row = c >> 2;
            int off8 = (c & 3) * 8;
            uint32_t dsto = (uint32_t)(ASE2 * 2) + (uint32_t)(row * LDP + off8) * 2u;
            cp16(stb + dsto, Wh + (size_t)(n0 + row) * Kd + k0 + off8);
        }
        cp_commit();
    };

    issue_stage(0, 0);
    if (nk > 1) issue_stage(1, 1);

    for (int kt = 0; kt < nk; ++kt) {
        if (kt + 2 < nk) { issue_stage((kt + 2) % 3, kt + 2); cp_wait<2>(); }
        else if (kt + 1 < nk) { cp_wait<1>(); }
        else { cp_wait<0>(); }
        __syncthreads();

        uint32_t stb = sbase + (uint32_t)(kt % 3) * STG2;
        #pragma unroll
        for (int kk = 0; kk < 32; kk += 16) {
            uint32_t Af[2][4], Bf[4][4];
            #pragma unroll
            for (int im = 0; im < 2; ++im) {
                uint32_t off = (uint32_t)((a_row + im * 16) * LDP + kk + a_coladd) * 2;
                ldsm_x4(Af[im], stb + off);
            }
            #pragma unroll
            for (int q = 0; q < 4; ++q) {
                uint32_t off = (uint32_t)(ASE2 * 2)
                             + (uint32_t)((b_row + q * 16) * LDP + kk + b_coladd) * 2;
                ldsm_x4(Bf[q], stb + off);
            }
            #pragma unroll
            for (int im = 0; im < 2; ++im)
                #pragma unroll
                for (int q = 0; q < 4; ++q)
                    #pragma unroll
                    for (int hf = 0; hf < 2; ++hf)
                        mma_f16(acc[im][q * 2 + hf], Af[im], &Bf[q][hf * 2]);
        }
        __syncthreads();
    }

    // epilogue
    #pragma unroll
    for (int im = 0; im < 2; ++im) {
        int r0 = m0 + wm + im * 16 + (lane >> 2);
        #pragma unroll
        for (int jn = 0; jn < 8; ++jn) {
            int c0 = n0 + wn + jn * 8 + (lane & 3) * 2;
            float b0 = 0.f, b1 = 0.f;
            if (EPI != 0) { b0 = bias[c0]; b1 = bias[c0 + 1]; }
            float z[4] = {acc[im][jn][0], acc[im][jn][1],
                          acc[im][jn][2], acc[im][jn][3]};
            #pragma unroll
            for (int e = 0; e < 4; ++e) {
                float bb = (e & 1) ? b1 : b0;
                float v = z[e];
                if (EPI == 1) { v += bb; v = 1.0f / (1.0f + expf(-v)); }
                else if (EPI == 2) { v += bb; v = v / (1.0f + expf(-v)); }
                z[e] = v;
            }
            size_t o0 = (size_t)r0 * N + c0;
            size_t o1 = (size_t)(r0 + 8) * N + c0;
            if (EPI == 2) {
                *(__half2*)&Ch[o0] = __floats2half2_rn(z[0], z[1]);
                *(__half2*)&Ch[o1] = __floats2half2_rn(z[2], z[3]);
            } else {
                if (EPI == 3) {
                    z[0] += b0 + res[o0]; z[1] += b1 + res[o0 + 1];
                    z[2] += b0 + res[o1]; z[3] += b1 + res[o1 + 1];
                }
                *(float2*)&Cout[o0] = make_float2(z[0], z[1]);
                *(float2*)&Cout[o1] = make_float2(z[2], z[3]);
            }
        }
    }
}

// ---------------------------------------------------------------------------
// Launch
// ---------------------------------------------------------------------------
extern "C" void kernel_launch(void* const* d_in, const int* in_sizes, int n_in,
                              void* d_out, int out_size)
{
    const float* x         = (const float*)d_in[0];
    const float* w_in      = (const float*)d_in[1];
    const float* w_out     = (const float*)d_in[2];
    const float* w_gate    = (const float*)d_in[3];
    const float* b_gate    = (const float*)d_in[4];
    const float* log_decay = (const float*)d_in[5];
    const float* frequency = (const float*)d_in[6];
    const float* coupling  = (const float*)d_in[7];
    const float* w_mlp1    = (const float*)d_in[8];
    const float* b_mlp1    = (const float*)d_in[9];
    const float* w_mlp2    = (const float*)d_in[10];
    const float* b_mlp2    = (const float*)d_in[11];
    const float* ln1_g     = (const float*)d_in[12];
    const float* ln1_b     = (const float*)d_in[13];
    const float* ln2_g     = (const float*)d_in[14];
    const float* ln2_b     = (const float*)d_in[15];
    float* out = (float*)d_out;

    __half *xn, *cb, *x2, *hid;
    __half *winh, *wgth, *wouth, *wm1h, *wm2h;
    float *beta, *gate, *hbuf, *x1;
    cudaGetSymbolAddress((void**)&xn,   g_xn);
    cudaGetSymbolAddress((void**)&beta, g_beta);
    cudaGetSymbolAddress((void**)&cb,   g_c);
    cudaGetSymbolAddress((void**)&gate, g_gate);
    cudaGetSymbolAddress((void**)&hbuf, g_h);
    cudaGetSymbolAddress((void**)&x1,   g_x1);
    cudaGetSymbolAddress((void**)&x2,   g_x2);
    cudaGetSymbolAddress((void**)&hid,  g_hid);
    cudaGetSymbolAddress((void**)&winh,  g_win_h);
    cudaGetSymbolAddress((void**)&wgth,  g_wgt_h);
    cudaGetSymbolAddress((void**)&wouth, g_wout_h);
    cudaGetSymbolAddress((void**)&wm1h,  g_wm1_h);
    cudaGetSymbolAddress((void**)&wm2h,  g_wm2_h);

    cudaFuncSetAttribute(mma_gemm_narrow,  cudaFuncAttributeMaxDynamicSharedMemorySize, GEMM_SMEM_N);
    cudaFuncSetAttribute(mma_gemm_bigm<0>, cudaFuncAttributeMaxDynamicSharedMemorySize, GEMM_SMEM_B);
    cudaFuncSetAttribute(mma_gemm_bigm<1>, cudaFuncAttributeMaxDynamicSharedMemorySize, GEMM_SMEM_B);
    cudaFuncSetAttribute(mma_gemm_bigm<2>, cudaFuncAttributeMaxDynamicSharedMemorySize, GEMM_SMEM_B);
    cudaFuncSetAttribute(mma_gemm_bigm<3>, cudaFuncAttributeMaxDynamicSharedMemorySize, GEMM_SMEM_B);

    // 0. weights -> fp16
    wconv_kernel<<<(2*Kk*Dd/4 + 255)/256, 256>>>(w_in,   winh,  2*Kk*Dd/4);
    wconv_kernel<<<(Dd*Dd/4 + 255)/256, 256>>>(w_gate,  wgth,  Dd*Dd/4);
    wconv_kernel<<<(Dd*2*Kk/4 + 255)/256, 256>>>(w_out, wouth, Dd*2*Kk/4);
    wconv_kernel<<<(MLPd*Dd/4 + 255)/256, 256>>>(w_mlp1, wm1h, MLPd*Dd/4);
    wconv_kernel<<<(Dd*MLPd/4 + 255)/256, 256>>>(w_mlp2, wm2h, Dd*MLPd/4);

    // 1. LN1 -> xnorm fp16
    ln_kernel<<<Ntok, 256>>>(x, ln1_g, ln1_b, xn);
    // 2. beta = xnorm @ w_in^T   (16384 x 128 x 1024), narrow kernel
    mma_gemm_narrow<<<dim3(1, Ntok/128), 256, GEMM_SMEM_N>>>(
        xn, winh, beta, Ntok, 128, Dd);
    // 3. intra-chunk backward scan (in place, fp32)
    phaseA_kernel<<<64, 256>>>(beta, log_decay, frequency);
    // 4. carry + coupling -> c fp16
    phaseC_kernel<<<Ntok, 128>>>(beta, coupling, cb);
    // 5. gate = sigmoid(xnorm @ w_gate^T + b_gate)
    mma_gemm_bigm<1><<<dim3(Dd/128, Ntok/256), 512, GEMM_SMEM_B>>>(
        xn, wgth, b_gate, nullptr, gate, nullptr, Ntok, Dd, Dd);
    // 6. h = c @ w_out^T   (K = 128)
    mma_gemm_bigm<0><<<dim3(Dd/128, Ntok/256), 512, GEMM_SMEM_B>>>(
        cb, wouth, nullptr, nullptr, hbuf, nullptr, Ntok, Dd, 2*Kk);
    // 7. x1 = x + gate*h ; x2n = LN2(x1) -> fp16
    combine_ln2_kernel<<<Ntok, 256>>>(x, gate, hbuf, ln2_g, ln2_b, x1, x2);
    // 8. hid = silu(x2n @ w_mlp1^T + b1) -> fp16
    mma_gemm_bigm<2><<<dim3(MLPd/128, Ntok/256), 512, GEMM_SMEM_B>>>(
        x2, wm1h, b_mlp1, nullptr, nullptr, hid, Ntok, MLPd, Dd);
    // 9. out = hid @ w_mlp2^T + b2 + x1
    mma_gemm_bigm<3><<<dim3(Dd/128, Ntok/256), 512, GEMM_SMEM_B>>>(
        hid, wm2h, b_mlp2, x1, out, nullptr, Ntok, Dd, MLPd);
    (void)in_sizes; (void)n_in; (void)out_size;
}

// round 15
// speedup vs baseline: 1.1923x; 1.1384x over previous
#include <cuda_runtime.h>
#include <cuda_fp16.h>
#include <cstdint>
#include <cmath>

// ---------------------------------------------------------------------------
// Problem constants
// ---------------------------------------------------------------------------
#define Bb 4
#define Tt 4096
#define Dd 1024
#define Kk 64
#define Hh 4
#define KHh 16
#define Cc 64
#define MLPd 4096
#define Ntok (Bb * Tt)          // 16384 tokens

// ---------------------------------------------------------------------------
// Scratch (static __device__ arrays; no allocation anywhere)
// ---------------------------------------------------------------------------
__device__ __half g_xn  [(size_t)Ntok * Dd];
__device__ float  g_beta[(size_t)Ntok * 2 * Kk];
__device__ __half g_c   [(size_t)Ntok * 2 * Kk];
__device__ float  g_gate[(size_t)Ntok * Dd];
__device__ float  g_h   [(size_t)Ntok * Dd];
__device__ float  g_x1  [(size_t)Ntok * Dd];
__device__ __half g_x2  [(size_t)Ntok * Dd];
__device__ __half g_hid [(size_t)Ntok * MLPd];
// fp16 weights
__device__ __half g_win_h [2 * Kk * Dd];
__device__ __half g_wgt_h [Dd * Dd];
__device__ __half g_wout_h[Dd * 2 * Kk];
__device__ __half g_wm1_h [(size_t)MLPd * Dd];
__device__ __half g_wm2_h [(size_t)Dd * MLPd];

// ---------------------------------------------------------------------------
// Weight convert: fp32 -> fp16
// ---------------------------------------------------------------------------
__global__ void __launch_bounds__(256) wconv_kernel(
    const float* __restrict__ in, __half* __restrict__ out, int n4)
{
    int i = blockIdx.x * 256 + threadIdx.x;
    if (i >= n4) return;
    float4 v = ((const float4*)in)[i];
    size_t o = (size_t)i * 4;
    *(__half2*)&out[o]     = __floats2half2_rn(v.x, v.y);
    *(__half2*)&out[o + 2] = __floats2half2_rn(v.z, v.w);
}

// ---------------------------------------------------------------------------
// LayerNorm -> fp16 (one block per row of 1024)
// ---------------------------------------------------------------------------
__global__ void __launch_bounds__(256) ln_kernel(
    const float* __restrict__ x, const float* __restrict__ gg,
    const float* __restrict__ bb, __half* __restrict__ outh)
{
    int row = blockIdx.x;
    int tid = threadIdx.x;
    float4 v = ((const float4*)(x + (size_t)row * Dd))[tid];
    float s  = v.x + v.y + v.z + v.w;
    float ss = v.x*v.x + v.y*v.y + v.z*v.z + v.w*v.w;
    #pragma unroll
    for (int o = 16; o; o >>= 1) {
        s  += __shfl_down_sync(0xffffffffu, s,  o);
        ss += __shfl_down_sync(0xffffffffu, ss, o);
    }
    __shared__ float sh_s[8], sh_ss[8];
    __shared__ float sh_m, sh_r;
    int w = tid >> 5, lane = tid & 31;
    if (!lane) { sh_s[w] = s; sh_ss[w] = ss; }
    __syncthreads();
    if (tid == 0) {
        float S = 0.f, SS = 0.f;
        #pragma unroll
        for (int i = 0; i < 8; ++i) { S += sh_s[i]; SS += sh_ss[i]; }
        float m = S * (1.0f / Dd);
        sh_m = m;
        sh_r = rsqrtf(SS * (1.0f / Dd) - m * m + 1e-5f);
    }
    __syncthreads();
    float m = sh_m, r = sh_r;
    float4 g4 = ((const float4*)gg)[tid];
    float4 b4 = ((const float4*)bb)[tid];
    float ox = (v.x - m) * r * g4.x + b4.x;
    float oy = (v.y - m) * r * g4.y + b4.y;
    float oz = (v.z - m) * r * g4.z + b4.z;
    float ow = (v.w - m) * r * g4.w + b4.w;
    size_t o = (size_t)row * Dd + tid * 4;
    *(__half2*)&outh[o]     = __floats2half2_rn(ox, oy);
    *(__half2*)&outh[o + 2] = __floats2half2_rn(oz, ow);
}

// ---------------------------------------------------------------------------
// x1 = x + gate*h ; x2n = LN(x1) -> fp16.  One block per row.
// ---------------------------------------------------------------------------
__global__ void __launch_bounds__(256) combine_ln2_kernel(
    const float* __restrict__ x, const float* __restrict__ gate,
    const float* __restrict__ h, const float* __restrict__ g2,
    const float* __restrict__ b2, float* __restrict__ x1,
    __half* __restrict__ outh)
{
    int row = blockIdx.x;
    int tid = threadIdx.x;
    size_t off = (size_t)row * 256 + tid;
    float4 xv = ((const float4*)x)[off];
    float4 gv = ((const float4*)gate)[off];
    float4 hv = ((const float4*)h)[off];
    float4 v;
    v.x = xv.x + gv.x * hv.x;
    v.y = xv.y + gv.y * hv.y;
    v.z = xv.z + gv.z * hv.z;
    v.w = xv.w + gv.w * hv.w;
    ((float4*)x1)[off] = v;

    float s  = v.x + v.y + v.z + v.w;
    float ss = v.x*v.x + v.y*v.y + v.z*v.z + v.w*v.w;
    #pragma unroll
    for (int o = 16; o; o >>= 1) {
        s  += __shfl_down_sync(0xffffffffu, s,  o);
        ss += __shfl_down_sync(0xffffffffu, ss, o);
    }
    __shared__ float sh_s[8], sh_ss[8];
    __shared__ float sh_m, sh_r;
    int w = tid >> 5, lane = tid & 31;
    if (!lane) { sh_s[w] = s; sh_ss[w] = ss; }
    __syncthreads();
    if (tid == 0) {
        float S = 0.f, SS = 0.f;
        #pragma unroll
        for (int i = 0; i < 8; ++i) { S += sh_s[i]; SS += sh_ss[i]; }
        float m = S * (1.0f / Dd);
        sh_m = m;
        sh_r = rsqrtf(SS * (1.0f / Dd) - m * m + 1e-5f);
    }
    __syncthreads();
    float m = sh_m, r = sh_r;
    float4 g4 = ((const float4*)g2)[tid];
    float4 b4 = ((const float4*)b2)[tid];
    float ox = (v.x - m) * r * g4.x + b4.x;
    float oy = (v.y - m) * r * g4.y + b4.y;
    float oz = (v.z - m) * r * g4.z + b4.z;
    float ow = (v.w - m) * r * g4.w + b4.w;
    size_t o = off * 4;
    *(__half2*)&outh[o]     = __floats2half2_rn(ox, oy);
    *(__half2*)&outh[o + 2] = __floats2half2_rn(oz, ow);
}

// ---------------------------------------------------------------------------
// Phase A: intra-chunk BACKWARD complex scan, in place (fp32).
// ---------------------------------------------------------------------------
__global__ void __launch_bounds__(256) phaseA_kernel(
    float* __restrict__ beta, const float* __restrict__ ld,
    const float* __restrict__ fr)
{
    int tid = blockIdx.x * 256 + threadIdx.x;
    int k = tid & 63;
    int chunk = (tid >> 6) & 63;
    int b = tid >> 12;
    float mag = 1.0f / (1.0f + expf(-ld[k]));
    float f = fr[k];
    float lr = mag * cosf(f), li = mag * sinf(f);
    size_t base = ((size_t)(b * Tt + chunk * Cc)) * 128 + k;
    float cr = 0.f, ci = 0.f;
    for (int j = Cc - 1; j >= 0; --j) {
        size_t idx = base + (size_t)j * 128;
        float br = beta[idx];
        float bi = beta[idx + 64];
        float nr = br + lr * cr - li * ci;
        float ni = bi + lr * ci + li * cr;
        cr = nr; ci = ni;
        beta[idx]      = cr;
        beta[idx + 64] = ci;
    }
}

// ---------------------------------------------------------------------------
// Phase C: carry + 16x16 coupling -> fp16.  One block per token.
// ---------------------------------------------------------------------------
__global__ void __launch_bounds__(128) phaseC_kernel(
    const float* __restrict__ intra, const float* __restrict__ coup,
    __half* __restrict__ cout)
{
    int tg = blockIdx.x;
    int t = tg & (Tt - 1);
    int tid = threadIdx.x;

    __shared__ float cs[128];
    __shared__ float coups[Hh * KHh * KHh];
    #pragma unroll
    for (int i = tid; i < Hh * KHh * KHh; i += 128) coups[i] = coup[i];

    if (tid < 64) {
        int k = tid;
        size_t ib = (size_t)tg * 128 + k;
        float ir = intra[ib];
        float ii = intra[ib + 64];
        if (((t & (Cc - 1)) == 0) && (t > 0)) {
            size_t pb = (size_t)(tg - 1) * 128 + k;
            ir += intra[pb];
            ii += intra[pb + 64];
        }
        cs[k]      = ir;
        cs[64 + k] = ii;
    }
    __syncthreads();

    int m = tid;
    int part = m >> 6;
    int mm = m & 63;
    int hh = mm >> 4, j = mm & 15;
    const float* cp = &coups[(hh * KHh + j) * KHh];
    const float* cv = &cs[part * 64 + hh * KHh];
    float acc = 0.f;
    #pragma unroll
    for (int k = 0; k < KHh; ++k) acc += cp[k] * cv[k];
    cout[(size_t)tg * 128 + m] = __float2half_rn(acc);
}

// ---------------------------------------------------------------------------
// MMA helpers
// ---------------------------------------------------------------------------
__device__ __forceinline__ void ldsm_x4(uint32_t* r, uint32_t addr) {
    asm volatile("ldmatrix.sync.aligned.m8n8.x4.shared.b16 {%0,%1,%2,%3}, [%4];"
                 : "=r"(r[0]), "=r"(r[1]), "=r"(r[2]), "=r"(r[3]) : "r"(addr));
}
__device__ __forceinline__ void mma_f16(float* d, const uint32_t* a, const uint32_t* b) {
    asm volatile(
        "mma.sync.aligned.m16n8k16.row.col.f32.f16.f16.f32 "
        "{%0,%1,%2,%3}, {%4,%5,%6,%7}, {%8,%9}, {%0,%1,%2,%3};"
        : "+f"(d[0]), "+f"(d[1]), "+f"(d[2]), "+f"(d[3])
        : "r"(a[0]), "r"(a[1]), "r"(a[2]), "r"(a[3]), "r"(b[0]), "r"(b[1]));
}
__device__ __forceinline__ void cp16(uint32_t d, const void* s) {
    asm volatile("cp.async.cg.shared.global [%0], [%1], 16;" :: "r"(d), "l"(s));
}
__device__ __forceinline__ void cp_commit() {
    asm volatile("cp.async.commit_group;");
}
template <int Nn> __device__ __forceinline__ void cp_wait() {
    asm volatile("cp.async.wait_group %0;" :: "n"(Nn));
}

#define LDP 40                       // padded fp16 row stride
#define TSE (128 * LDP)              // elems per smem array
#define STG1 (2 * TSE * 2)           // bytes per stage (A + B) = 20480
#define GEMM_SMEM (3 * STG1)         // 3 stages = 61440 B

// ---------------------------------------------------------------------------
// GEMM: 128x128 CTA tile, 256 thr, 8 warps (4m x 2n), warp tile 32x64.
// 3-stage cp.async pipeline, ONE __syncthreads per k-tile:
//   wait(stage kt) -> sync -> issue stage (kt+2)%3 -> compute stage kt%3.
// With 3 stages the refill target was last read in iteration kt-1; every
// warp passing this iteration's barrier proves that read is complete.
// EPI: 0 fp32; 1 sigmoid(z+b); 2 silu(z+b)->fp16; 3 z+b+res
// ---------------------------------------------------------------------------
template <int EPI>
__global__ void __launch_bounds__(256) mma_gemm_1h(
    const __half* __restrict__ A, const __half* __restrict__ Wh,
    const float* __restrict__ bias, const float* __restrict__ res,
    float* __restrict__ Cout, __half* __restrict__ Ch,
    int M, int N, int Kd)
{
    extern __shared__ __half sm[];

    int t = threadIdx.x;
    int lane = t & 31, w = t >> 5;
    int wm = (w & 3) * 32;
    int wn = (w >> 2) * 64;
    int m0 = blockIdx.y * 128;
    int n0 = blockIdx.x * 128;

    int a_row = wm + (lane & 15);
    int a_coladd = (lane >> 4) << 3;
    int b_row = wn + (lane & 7) + ((lane >> 4) << 3);
    int b_coladd = ((lane >> 3) & 1) << 3;

    uint32_t sbase = (uint32_t)__cvta_generic_to_shared(sm);

    float acc[2][8][4];
    #pragma unroll
    for (int i = 0; i < 2; ++i)
        #pragma unroll
        for (int j = 0; j < 8; ++j)
            #pragma unroll
            for (int e = 0; e < 4; ++e) acc[i][j][e] = 0.f;

    int nk = Kd >> 5;

    auto issue_stage = [&](int s, int kt) {
        uint32_t stb = sbase + (uint32_t)s * STG1;
        int k0 = kt * 32;
        #pragma unroll
        for (int it = 0; it < 2; ++it) {
            int c = t + it * 256;          // 0..511
            int row = c >> 2;
            int off8 = (c & 3) * 8;        // 0,8,16,24 elems = 16B chunks
            uint32_t dsto = (uint32_t)(row * LDP + off8) * 2u;
            cp16(stb + dsto,                       A  + (size_t)(m0 + row) * Kd + k0 + off8);
            cp16(stb + (uint32_t)(TSE * 2) + dsto, Wh + (size_t)(n0 + row) * Kd + k0 + off8);
        }
        cp_commit();
    };

    issue_stage(0, 0);
    if (nk > 1) issue_stage(1, 1);

    for (int kt = 0; kt < nk; ++kt) {
        // wait until stage kt%3's group is complete
        if (kt + 1 < nk) cp_wait<1>(); else cp_wait<0>();
        __syncthreads();
        // refill the stage last read at iteration kt-1 (safe: all warps
        // passed the barrier above, so that read is done)
        if (kt + 2 < nk) issue_stage((kt + 2) % 3, kt + 2);

        uint32_t stb = sbase + (uint32_t)(kt % 3) * STG1;
        #pragma unroll
        for (int kk = 0; kk < 32; kk += 16) {
            uint32_t Af[2][4], Bf[4][4];
            #pragma unroll
            for (int im = 0; im < 2; ++im) {
                uint32_t off = (uint32_t)((a_row + im * 16) * LDP + kk + a_coladd) * 2;
                ldsm_x4(Af[im], stb + off);
            }
            #pragma unroll
            for (int q = 0; q < 4; ++q) {
                uint32_t off = (uint32_t)((b_row + q * 16) * LDP + kk + b_coladd) * 2;
                ldsm_x4(Bf[q], stb + (uint32_t)(TSE * 2) + off);
            }
            #pragma unroll
            for (int im = 0; im < 2; ++im)
                #pragma unroll
                for (int q = 0; q < 4; ++q)
                    #pragma unroll
                    for (int hf = 0; hf < 2; ++hf)
                        mma_f16(acc[im][q * 2 + hf], Af[im], &Bf[q][hf * 2]);
        }
    }

    // epilogue
    #pragma unroll
    for (int im = 0; im < 2; ++im) {
        int r0 = m0 + wm + im * 16 + (lane >> 2);
        #pragma unroll
        for (int jn = 0; jn < 8; ++jn) {
            int c0 = n0 + wn + jn * 8 + (lane & 3) * 2;
            float b0 = 0.f, b1 = 0.f;
            if (EPI != 0) { b0 = bias[c0]; b1 = bias[c0 + 1]; }
            float z[4] = {acc[im][jn][0], acc[im][jn][1],
                          acc[im][jn][2], acc[im][jn][3]};
            #pragma unroll
            for (int e = 0; e < 4; ++e) {
                float bb = (e & 1) ? b1 : b0;
                float v = z[e];
                if (EPI == 1) { v += bb; v = 1.0f / (1.0f + expf(-v)); }
                else if (EPI == 2) { v += bb; v = v / (1.0f + expf(-v)); }
                z[e] = v;
            }
            size_t o0 = (size_t)r0 * N + c0;
            size_t o1 = (size_t)(r0 + 8) * N + c0;
            if (EPI == 2) {
                *(__half2*)&Ch[o0] = __floats2half2_rn(z[0], z[1]);
                *(__half2*)&Ch[o1] = __floats2half2_rn(z[2], z[3]);
            } else {
                if (EPI == 3) {
                    z[0] += b0 + res[o0]; z[1] += b1 + res[o0 + 1];
                    z[2] += b0 + res[o1]; z[3] += b1 + res[o1 + 1];
                }
                *(float2*)&Cout[o0] = make_float2(z[0], z[1]);
                *(float2*)&Cout[o1] = make_float2(z[2], z[3]);
            }
        }
    }
}

// ---------------------------------------------------------------------------
// Launch
// ---------------------------------------------------------------------------
extern "C" void kernel_launch(void* const* d_in, const int* in_sizes, int n_in,
                              void* d_out, int out_size)
{
    const float* x         = (const float*)d_in[0];
    const float* w_in      = (const float*)d_in[1];
    const float* w_out     = (const float*)d_in[2];
    const float* w_gate    = (const float*)d_in[3];
    const float* b_gate    = (const float*)d_in[4];
    const float* log_decay = (const float*)d_in[5];
    const float* frequency = (const float*)d_in[6];
    const float* coupling  = (const float*)d_in[7];
    const float* w_mlp1    = (const float*)d_in[8];
    const float* b_mlp1    = (const float*)d_in[9];
    const float* w_mlp2    = (const float*)d_in[10];
    const float* b_mlp2    = (const float*)d_in[11];
    const float* ln1_g     = (const float*)d_in[12];
    const float* ln1_b     = (const float*)d_in[13];
    const float* ln2_g     = (const float*)d_in[14];
    const float* ln2_b     = (const float*)d_in[15];
    float* out = (float*)d_out;

    __half *xn, *cb, *x2, *hid;
    __half *winh, *wgth, *wouth, *wm1h, *wm2h;
    float *beta, *gate, *hbuf, *x1;
    cudaGetSymbolAddress((void**)&xn,   g_xn);
    cudaGetSymbolAddress((void**)&beta, g_beta);
    cudaGetSymbolAddress((void**)&cb,   g_c);
    cudaGetSymbolAddress((void**)&gate, g_gate);
    cudaGetSymbolAddress((void**)&hbuf, g_h);
    cudaGetSymbolAddress((void**)&x1,   g_x1);
    cudaGetSymbolAddress((void**)&x2,   g_x2);
    cudaGetSymbolAddress((void**)&hid,  g_hid);
    cudaGetSymbolAddress((void**)&winh,  g_win_h);
    cudaGetSymbolAddress((void**)&wgth,  g_wgt_h);
    cudaGetSymbolAddress((void**)&wouth, g_wout_h);
    cudaGetSymbolAddress((void**)&wm1h,  g_wm1_h);
    cudaGetSymbolAddress((void**)&wm2h,  g_wm2_h);

    cudaFuncSetAttribute(mma_gemm_1h<0>, cudaFuncAttributeMaxDynamicSharedMemorySize, GEMM_SMEM);
    cudaFuncSetAttribute(mma_gemm_1h<1>, cudaFuncAttributeMaxDynamicSharedMemorySize, GEMM_SMEM);
    cudaFuncSetAttribute(mma_gemm_1h<2>, cudaFuncAttributeMaxDynamicSharedMemorySize, GEMM_SMEM);
    cudaFuncSetAttribute(mma_gemm_1h<3>, cudaFuncAttributeMaxDynamicSharedMemorySize, GEMM_SMEM);

    // 0. weights -> fp16
    wconv_kernel<<<(2*Kk*Dd/4 + 255)/256, 256>>>(w_in,   winh,  2*Kk*Dd/4);
    wconv_kernel<<<(Dd*Dd/4 + 255)/256, 256>>>(w_gate,  wgth,  Dd*Dd/4);
    wconv_kernel<<<(Dd*2*Kk/4 + 255)/256, 256>>>(w_out, wouth, Dd*2*Kk/4);
    wconv_kernel<<<(MLPd*Dd/4 + 255)/256, 256>>>(w_mlp1, wm1h, MLPd*Dd/4);
    wconv_kernel<<<(Dd*MLPd/4 + 255)/256, 256>>>(w_mlp2, wm2h, Dd*MLPd/4);

    // 1. LN1 -> xnorm fp16
    ln_kernel<<<Ntok, 256>>>(x, ln1_g, ln1_b, xn);
    // 2. beta = xnorm @ w_in^T   (16384 x 128 x 1024), fp32 out
    mma_gemm_1h<0><<<dim3(1, Ntok/128), 256, GEMM_SMEM>>>(
        xn, winh, nullptr, nullptr, beta, nullptr, Ntok, 128, Dd);
    // 3. intra-chunk backward scan (in place, fp32)
    phaseA_kernel<<<64, 256>>>(beta, log_decay, frequency);
    // 4. carry + coupling -> c fp16
    phaseC_kernel<<<Ntok, 128>>>(beta, coupling, cb);
    // 5. gate = sigmoid(xnorm @ w_gate^T + b_gate), fp32 out
    mma_gemm_1h<1><<<dim3(Dd/128, Ntok/128), 256, GEMM_SMEM>>>(
        xn, wgth, b_gate, nullptr, gate, nullptr, Ntok, Dd, Dd);
    // 6. h = c @ w_out^T   (16384 x 1024 x 128), fp32 out
    mma_gemm_1h<0><<<dim3(Dd/128, Ntok/128), 256, GEMM_SMEM>>>(
        cb, wouth, nullptr, nullptr, hbuf, nullptr, Ntok, Dd, 2*Kk);
    // 7. x1 = x + gate*h ; x2n = LN2(x1) -> fp16
    combine_ln2_kernel<<<Ntok, 256>>>(x, gate, hbuf, ln2_g, ln2_b, x1, x2);
    // 8. hid = silu(x2n @ w_mlp1^T + b1) -> fp16 out
    mma_gemm_1h<2><<<dim3(MLPd/128, Ntok/128), 256, GEMM_SMEM>>>(
        x2, wm1h, b_mlp1, nullptr, nullptr, hid, Ntok, MLPd, Dd);
    // 9. out = hid @ w_mlp2^T + b2 + x1, fp32 out
    mma_gemm_1h<3><<<dim3(Dd/128, Ntok/128), 256, GEMM_SMEM>>>(
        hid, wm2h, b_mlp2, x1, out, nullptr, Ntok, Dd, MLPd);
    (void)in_sizes; (void)n_in; (void)out_size;
}